// round 11
// baseline (speedup 1.0000x reference)
#include <cuda_runtime.h>
#include <cstdint>

// Inputs (metadata order):
//   d_in[0] = g     : float32 [N, N]   (N*N elements)
//   d_in[1] = h     : float32 [n, D]   (n*D elements)
//   d_in[2] = pre_h : float32 [N, D]   (N*D elements)  (unused)
//   d_in[3] = idx   : int32   [n]      (sorted unique)
// Output: concat( g [N*N], new_h [N*D] ) float32.
//
// Fused one-wave kernel (1184 blocks = 8/SM x 148 SMs, 32 regs):
//   blocks [0,1120):    copy g[0, split4)           (MLP=4 float4 loop)
//   blocks [1120,1184): fill new_h (two-pointer walk, ~15 us), then
//                       copy g[split4, g4)          (same loop, own stride)
// split4 gives fill blocks ~4.5% of g so both legs finish together.

#define TOTAL_BLOCKS 1184
#define COPY_BLOCKS  1120
#define FILL_BLOCKS  (TOTAL_BLOCKS - COPY_BLOCKS)
#define THREADS      256
#define WARPS_PER_BLOCK (THREADS / 32)
#define FILL_WARPS   (FILL_BLOCKS * WARPS_PER_BLOCK)   // 512

__device__ __forceinline__ void copy_range_f4(const float4* __restrict__ src,
                                              float4* __restrict__ dst,
                                              long long begin, long long end,
                                              long long stride,
                                              long long first) {
    long long i = begin + first;
    long long limit = end - 3 * stride;
    for (; i < limit; i += 4 * stride) {
        float4 a = src[i];
        float4 b = src[i + stride];
        float4 c = src[i + 2 * stride];
        float4 d = src[i + 3 * stride];
        dst[i]              = a;
        dst[i + stride]     = b;
        dst[i + 2 * stride] = c;
        dst[i + 3 * stride] = d;
    }
    for (; i < end; i += stride) {
        dst[i] = src[i];
    }
}

__global__ void __launch_bounds__(THREADS, 8)
fused_unpool_kernel(const float4* __restrict__ g,
                    const float4* __restrict__ h,
                    const int* __restrict__ idx,
                    float4* __restrict__ out_g,
                    float4* __restrict__ out_newh,
                    long long g4, long long split4,
                    int n_rows, int n_idx, int d4) {
    if (blockIdx.x < COPY_BLOCKS) {
        // ------- main copy leg: g[0, split4) -------
        const long long stride = (long long)COPY_BLOCKS * THREADS;
        const long long first = (long long)blockIdx.x * THREADS + threadIdx.x;
        copy_range_f4(g, out_g, 0, split4, stride, first);
    } else {
        // ------- fill new_h: contiguous rows per warp, two-pointer walk ----
        const int warp_id = (blockIdx.x - COPY_BLOCKS) * WARPS_PER_BLOCK
                            + (int)(threadIdx.x >> 5);
        const int lane = (int)(threadIdx.x & 31);

        const int rows_per_warp = (n_rows + FILL_WARPS - 1) / FILL_WARPS;
        int r0 = warp_id * rows_per_warp;
        int r1 = r0 + rows_per_warp;
        if (r1 > n_rows) r1 = n_rows;

        if (r0 < r1) {
            // One binary search: j = lower_bound(idx, r0).
            int lo = 0, hi = n_idx;
            while (lo < hi) {
                int mid = (lo + hi) >> 1;
                if (idx[mid] < r0) lo = mid + 1;
                else hi = mid;
            }
            int j = lo;

            const float4 z = make_float4(0.f, 0.f, 0.f, 0.f);
            for (int r = r0; r < r1; ++r) {
                bool kept = false;
                if (j < n_idx) {
                    if (idx[j] == r) kept = true;
                }
                float4* dst = out_newh + (long long)r * d4;
                if (kept) {
                    const float4* src = h + (long long)j * d4;
                    for (int c = lane; c < d4; c += 32) dst[c] = src[c];
                    ++j;
                } else {
                    for (int c = lane; c < d4; c += 32) dst[c] = z;
                }
            }
        }

        // ------- then join the copy: g[split4, g4) -------
        const long long stride = (long long)FILL_BLOCKS * THREADS;
        const long long first =
            (long long)(blockIdx.x - COPY_BLOCKS) * THREADS + threadIdx.x;
        copy_range_f4(g, out_g, split4, g4, stride, first);
    }
}

// Fallback fill-only kernel (out layout new_h-only).
__global__ void fill_newh_kernel(const float4* __restrict__ h,
                                 const int* __restrict__ idx,
                                 float4* __restrict__ new_h,
                                 int n_idx, int d4, long long total_f4) {
    long long t = (long long)blockIdx.x * blockDim.x + threadIdx.x;
    if (t >= total_f4) return;
    int r = (int)(t / d4);
    int c = (int)(t - (long long)r * d4);
    int lo = 0, hi = n_idx;
    while (lo < hi) {
        int mid = (lo + hi) >> 1;
        if (idx[mid] < r) lo = mid + 1;
        else hi = mid;
    }
    float4 v = make_float4(0.f, 0.f, 0.f, 0.f);
    if (lo < n_idx && idx[lo] == r) v = h[(long long)lo * d4 + c];
    new_h[t] = v;
}

// Fallback copy-only kernel (out layout g-only).
__global__ void __launch_bounds__(THREADS, 8)
copy_f4_kernel(const float4* __restrict__ src,
               float4* __restrict__ dst, long long n4) {
    const long long stride = (long long)gridDim.x * blockDim.x;
    const long long first = (long long)blockIdx.x * blockDim.x + threadIdx.x;
    copy_range_f4(src, dst, 0, n4, stride, first);
}

extern "C" void kernel_launch(void* const* d_in, const int* in_sizes, int n_in,
                              void* d_out, int out_size) {
    const float* g   = (const float*)d_in[0];
    const float* h   = (const float*)d_in[1];
    const int*   idx = (const int*)d_in[3];

    long long g_elems  = (long long)in_sizes[0];   // N*N
    long long h_elems  = (long long)in_sizes[1];   // n*D
    long long ph_elems = (long long)in_sizes[2];   // N*D
    long long n_idx    = (long long)in_sizes[3];   // n

    int D  = (int)(h_elems / n_idx);               // 256
    int d4 = D / 4;                                // 64
    int n_rows = (int)(ph_elems / D);              // N

    long long osz = (long long)out_size;

    if (osz >= g_elems + ph_elems) {
        float* out_g    = (float*)d_out;
        float* out_newh = out_g + g_elems;
        long long g4 = g_elems / 4;
        // Fill blocks take ~4.5% of g (their proportional 5.4% share minus
        // the fill-work offset) so both legs finish together.
        long long b4 = (g4 * 9) / 200;
        long long split4 = g4 - b4;
        fused_unpool_kernel<<<TOTAL_BLOCKS, THREADS>>>(
            (const float4*)g, (const float4*)h, idx,
            (float4*)out_g, (float4*)out_newh,
            g4, split4, n_rows, (int)n_idx, d4);
    } else if (osz >= g_elems) {
        copy_f4_kernel<<<TOTAL_BLOCKS, THREADS>>>(
            (const float4*)g, (float4*)d_out, g_elems / 4);
    } else {
        long long total_f4 = ph_elems / 4;
        long long blocks = (total_f4 + THREADS - 1) / THREADS;
        fill_newh_kernel<<<(unsigned)blocks, THREADS>>>(
            (const float4*)h, idx, (float4*)d_out,
            (int)n_idx, d4, total_f4);
    }
}

// round 12
// speedup vs baseline: 1.0237x; 1.0237x over previous
#include <cuda_runtime.h>
#include <cstdint>

// Inputs (metadata order):
//   d_in[0] = g     : float32 [N, N]   (N*N elements)
//   d_in[1] = h     : float32 [n, D]   (n*D elements)
//   d_in[2] = pre_h : float32 [N, D]   (N*D elements)  (unused)
//   d_in[3] = idx   : int32   [n]      (sorted unique)
// Output: concat( g [N*N], new_h [N*D] ) float32.
//
// One-wave kernel (1184 blocks = 8/SM x 148 SMs, 32 regs), two phases run by
// ALL blocks:
//   phase 1: fill new_h — 3 rows/warp via two-pointer walk over sorted idx
//            (one binary search per warp), coalesced float4 row writes. ~5 us.
//   phase 2: whole chip copies g with the proven MLP=4 float4 loop. ~496 us.
// No inter-block sync needed: the phases touch disjoint output regions.

#define TOTAL_BLOCKS 1184
#define THREADS      256
#define WARPS_PER_BLOCK (THREADS / 32)
#define TOTAL_WARPS  (TOTAL_BLOCKS * WARPS_PER_BLOCK)   // 9472

__device__ __forceinline__ void copy_range_f4(const float4* __restrict__ src,
                                              float4* __restrict__ dst,
                                              long long end,
                                              long long stride,
                                              long long first) {
    long long i = first;
    long long limit = end - 3 * stride;
    for (; i < limit; i += 4 * stride) {
        float4 a = src[i];
        float4 b = src[i + stride];
        float4 c = src[i + 2 * stride];
        float4 d = src[i + 3 * stride];
        dst[i]              = a;
        dst[i + stride]     = b;
        dst[i + 2 * stride] = c;
        dst[i + 3 * stride] = d;
    }
    for (; i < end; i += stride) {
        dst[i] = src[i];
    }
}

__global__ void __launch_bounds__(THREADS, 8)
fused_unpool_kernel(const float4* __restrict__ g,
                    const float4* __restrict__ h,
                    const int* __restrict__ idx,
                    float4* __restrict__ out_g,
                    float4* __restrict__ out_newh,
                    long long g4,
                    int n_rows, int n_idx, int d4) {
    // ---------------- phase 1: fill new_h (all blocks) ----------------
    {
        const int warp_id = blockIdx.x * WARPS_PER_BLOCK
                            + (int)(threadIdx.x >> 5);
        const int lane = (int)(threadIdx.x & 31);

        const int rows_per_warp = (n_rows + TOTAL_WARPS - 1) / TOTAL_WARPS;
        int r0 = warp_id * rows_per_warp;
        int r1 = r0 + rows_per_warp;
        if (r1 > n_rows) r1 = n_rows;

        if (r0 < r1) {
            // One binary search: j = lower_bound(idx, r0).
            int lo = 0, hi = n_idx;
            while (lo < hi) {
                int mid = (lo + hi) >> 1;
                if (idx[mid] < r0) lo = mid + 1;
                else hi = mid;
            }
            int j = lo;

            const float4 z = make_float4(0.f, 0.f, 0.f, 0.f);
            for (int r = r0; r < r1; ++r) {
                bool kept = false;
                if (j < n_idx) {
                    if (idx[j] == r) kept = true;
                }
                float4* dst = out_newh + (long long)r * d4;
                if (kept) {
                    const float4* src = h + (long long)j * d4;
                    for (int c = lane; c < d4; c += 32) dst[c] = src[c];
                    ++j;
                } else {
                    for (int c = lane; c < d4; c += 32) dst[c] = z;
                }
            }
        }
    }

    // ---------------- phase 2: copy g (all blocks) ----------------
    {
        const long long stride = (long long)TOTAL_BLOCKS * THREADS;
        const long long first = (long long)blockIdx.x * THREADS + threadIdx.x;
        copy_range_f4(g, out_g, g4, stride, first);
    }
}

// Fallback fill-only kernel (out layout new_h-only).
__global__ void fill_newh_kernel(const float4* __restrict__ h,
                                 const int* __restrict__ idx,
                                 float4* __restrict__ new_h,
                                 int n_idx, int d4, long long total_f4) {
    long long t = (long long)blockIdx.x * blockDim.x + threadIdx.x;
    if (t >= total_f4) return;
    int r = (int)(t / d4);
    int c = (int)(t - (long long)r * d4);
    int lo = 0, hi = n_idx;
    while (lo < hi) {
        int mid = (lo + hi) >> 1;
        if (idx[mid] < r) lo = mid + 1;
        else hi = mid;
    }
    float4 v = make_float4(0.f, 0.f, 0.f, 0.f);
    if (lo < n_idx && idx[lo] == r) v = h[(long long)lo * d4 + c];
    new_h[t] = v;
}

// Fallback copy-only kernel (out layout g-only).
__global__ void __launch_bounds__(THREADS, 8)
copy_f4_kernel(const float4* __restrict__ src,
               float4* __restrict__ dst, long long n4) {
    const long long stride = (long long)gridDim.x * blockDim.x;
    const long long first = (long long)blockIdx.x * blockDim.x + threadIdx.x;
    copy_range_f4(src, dst, n4, stride, first);
}

extern "C" void kernel_launch(void* const* d_in, const int* in_sizes, int n_in,
                              void* d_out, int out_size) {
    const float* g   = (const float*)d_in[0];
    const float* h   = (const float*)d_in[1];
    const int*   idx = (const int*)d_in[3];

    long long g_elems  = (long long)in_sizes[0];   // N*N
    long long h_elems  = (long long)in_sizes[1];   // n*D
    long long ph_elems = (long long)in_sizes[2];   // N*D
    long long n_idx    = (long long)in_sizes[3];   // n

    int D  = (int)(h_elems / n_idx);               // 256
    int d4 = D / 4;                                // 64
    int n_rows = (int)(ph_elems / D);              // N

    long long osz = (long long)out_size;

    if (osz >= g_elems + ph_elems) {
        float* out_g    = (float*)d_out;
        float* out_newh = out_g + g_elems;
        fused_unpool_kernel<<<TOTAL_BLOCKS, THREADS>>>(
            (const float4*)g, (const float4*)h, idx,
            (float4*)out_g, (float4*)out_newh,
            g_elems / 4, n_rows, (int)n_idx, d4);
    } else if (osz >= g_elems) {
        copy_f4_kernel<<<TOTAL_BLOCKS, THREADS>>>(
            (const float4*)g, (float4*)d_out, g_elems / 4);
    } else {
        long long total_f4 = ph_elems / 4;
        long long blocks = (total_f4 + THREADS - 1) / THREADS;
        fill_newh_kernel<<<(unsigned)blocks, THREADS>>>(
            (const float4*)h, idx, (float4*)d_out,
            (int)n_idx, d4, total_f4);
    }
}

// round 13
// speedup vs baseline: 1.0349x; 1.0110x over previous
#include <cuda_runtime.h>
#include <cstdint>

// Inputs (metadata order):
//   d_in[0] = g     : float32 [N, N]   (N*N elements)
//   d_in[1] = h     : float32 [n, D]   (n*D elements)
//   d_in[2] = pre_h : float32 [N, D]   (N*D elements)  (unused)
//   d_in[3] = idx   : int32   [n]      (sorted unique)
// Output: concat( g [N*N], new_h [N*D] ) float32.
//
// One-wave kernel (1184 blocks = 8/SM x 148 SMs, 32 regs), two phases run by
// ALL blocks:
//   phase 1: fill new_h — ~2 rows/warp via two-pointer walk over sorted idx
//            (one binary search per warp), coalesced float4 row writes. ~5 us.
//   phase 2: whole chip copies g with the MLP=4 float4 loop, evict-first
//            streaming hints via __ldcs/__stcs (compiler-managed regs). ~496 us.
// Phases touch disjoint output regions: no inter-block sync needed.

#define TOTAL_BLOCKS 1184
#define THREADS      256
#define WARPS_PER_BLOCK (THREADS / 32)
#define TOTAL_WARPS  (TOTAL_BLOCKS * WARPS_PER_BLOCK)   // 9472

__device__ __forceinline__ void copy_range_f4(const float4* __restrict__ src,
                                              float4* __restrict__ dst,
                                              long long end,
                                              long long stride,
                                              long long first) {
    long long i = first;
    long long limit = end - 3 * stride;
    for (; i < limit; i += 4 * stride) {
        float4 a = __ldcs(src + i);
        float4 b = __ldcs(src + i + stride);
        float4 c = __ldcs(src + i + 2 * stride);
        float4 d = __ldcs(src + i + 3 * stride);
        __stcs(dst + i,              a);
        __stcs(dst + i + stride,     b);
        __stcs(dst + i + 2 * stride, c);
        __stcs(dst + i + 3 * stride, d);
    }
    for (; i < end; i += stride) {
        __stcs(dst + i, __ldcs(src + i));
    }
}

__global__ void __launch_bounds__(THREADS, 8)
fused_unpool_kernel(const float4* __restrict__ g,
                    const float4* __restrict__ h,
                    const int* __restrict__ idx,
                    float4* __restrict__ out_g,
                    float4* __restrict__ out_newh,
                    long long g4,
                    int n_rows, int n_idx, int d4) {
    // ---------------- phase 1: fill new_h (all blocks) ----------------
    {
        const int warp_id = blockIdx.x * WARPS_PER_BLOCK
                            + (int)(threadIdx.x >> 5);
        const int lane = (int)(threadIdx.x & 31);

        const int rows_per_warp = (n_rows + TOTAL_WARPS - 1) / TOTAL_WARPS;
        int r0 = warp_id * rows_per_warp;
        int r1 = r0 + rows_per_warp;
        if (r1 > n_rows) r1 = n_rows;

        if (r0 < r1) {
            // One binary search: j = lower_bound(idx, r0).
            int lo = 0, hi = n_idx;
            while (lo < hi) {
                int mid = (lo + hi) >> 1;
                if (idx[mid] < r0) lo = mid + 1;
                else hi = mid;
            }
            int j = lo;

            const float4 z = make_float4(0.f, 0.f, 0.f, 0.f);
            for (int r = r0; r < r1; ++r) {
                bool kept = false;
                if (j < n_idx) {
                    if (idx[j] == r) kept = true;
                }
                float4* dst = out_newh + (long long)r * d4;
                if (kept) {
                    const float4* src = h + (long long)j * d4;
                    for (int c = lane; c < d4; c += 32) dst[c] = src[c];
                    ++j;
                } else {
                    for (int c = lane; c < d4; c += 32) dst[c] = z;
                }
            }
        }
    }

    // ---------------- phase 2: copy g (all blocks) ----------------
    {
        const long long stride = (long long)TOTAL_BLOCKS * THREADS;
        const long long first = (long long)blockIdx.x * THREADS + threadIdx.x;
        copy_range_f4(g, out_g, g4, stride, first);
    }
}

// Fallback fill-only kernel (out layout new_h-only).
__global__ void fill_newh_kernel(const float4* __restrict__ h,
                                 const int* __restrict__ idx,
                                 float4* __restrict__ new_h,
                                 int n_idx, int d4, long long total_f4) {
    long long t = (long long)blockIdx.x * blockDim.x + threadIdx.x;
    if (t >= total_f4) return;
    int r = (int)(t / d4);
    int c = (int)(t - (long long)r * d4);
    int lo = 0, hi = n_idx;
    while (lo < hi) {
        int mid = (lo + hi) >> 1;
        if (idx[mid] < r) lo = mid + 1;
        else hi = mid;
    }
    float4 v = make_float4(0.f, 0.f, 0.f, 0.f);
    if (lo < n_idx && idx[lo] == r) v = h[(long long)lo * d4 + c];
    new_h[t] = v;
}

// Fallback copy-only kernel (out layout g-only).
__global__ void __launch_bounds__(THREADS, 8)
copy_f4_kernel(const float4* __restrict__ src,
               float4* __restrict__ dst, long long n4) {
    const long long stride = (long long)gridDim.x * blockDim.x;
    const long long first = (long long)blockIdx.x * blockDim.x + threadIdx.x;
    copy_range_f4(src, dst, n4, stride, first);
}

extern "C" void kernel_launch(void* const* d_in, const int* in_sizes, int n_in,
                              void* d_out, int out_size) {
    const float* g   = (const float*)d_in[0];
    const float* h   = (const float*)d_in[1];
    const int*   idx = (const int*)d_in[3];

    long long g_elems  = (long long)in_sizes[0];   // N*N
    long long h_elems  = (long long)in_sizes[1];   // n*D
    long long ph_elems = (long long)in_sizes[2];   // N*D
    long long n_idx    = (long long)in_sizes[3];   // n

    int D  = (int)(h_elems / n_idx);               // 256
    int d4 = D / 4;                                // 64
    int n_rows = (int)(ph_elems / D);              // N

    long long osz = (long long)out_size;

    if (osz >= g_elems + ph_elems) {
        float* out_g    = (float*)d_out;
        float* out_newh = out_g + g_elems;
        fused_unpool_kernel<<<TOTAL_BLOCKS, THREADS>>>(
            (const float4*)g, (const float4*)h, idx,
            (float4*)out_g, (float4*)out_newh,
            g_elems / 4, n_rows, (int)n_idx, d4);
    } else if (osz >= g_elems) {
        copy_f4_kernel<<<TOTAL_BLOCKS, THREADS>>>(
            (const float4*)g, (float4*)d_out, g_elems / 4);
    } else {
        long long total_f4 = ph_elems / 4;
        long long blocks = (total_f4 + THREADS - 1) / THREADS;
        fill_newh_kernel<<<(unsigned)blocks, THREADS>>>(
            (const float4*)h, idx, (float4*)d_out,
            (int)n_idx, d4, total_f4);
    }
}